// round 17
// baseline (speedup 1.0000x reference)
#include <cuda_runtime.h>
#include <cuda_fp16.h>
#include <math.h>
#include <stdint.h>

constexpr int cB = 4, cN = 8192, cH = 1024, cNH = 16, cHM = 1024;

// ---------------- scratch (device globals) ----------------
__device__ __half g_xfh[(size_t)cB * cN * cH];   // x fp16 (row-major)
__device__ __half g_xtf[(size_t)cB * cH * cN];   // x^T fp16 (y-GEMM B)
__device__ __half g_Sf [(size_t)cB * cN * cHM];  // S fp16 (out-GEMM A)
__device__ __half g_Sft[(size_t)cB * cHM * cN];  // S^T fp16 (y-GEMM A)
__device__ __half g_Atf[cHM * cH];               // At fp16 [hm][j]
__device__ __half g_Ztf[(size_t)cB * cH * cHM];  // Z^T fp16 (out-GEMM B)
__device__ __half g_wtf[cNH * cH];               // w_temp^T fp16 [16][1024]
__device__ float g_c[cHM];
__device__ float g_T[cB * cN * cNH];
__device__ float g_norm[cB * cHM];
__device__ float g_yp[(size_t)8 * cB * cHM * cH];
__device__ float g_ost[cB * cNH * 64 * 64];

// ---------------- helpers ----------------
__device__ __forceinline__ uint32_t smem_u32(const void* p) {
    uint32_t a;
    asm("{ .reg .u64 t; cvta.to.shared.u64 t, %1; cvt.u32.u64 %0, t; }" : "=r"(a) : "l"(p));
    return a;
}
__device__ __forceinline__ void cp16(uint32_t s, const void* g) {
    asm volatile("cp.async.cg.shared.global [%0], [%1], 16;" :: "r"(s), "l"(g));
}
#define CP_COMMIT() asm volatile("cp.async.commit_group;" ::: "memory")
#define CP_WAIT2()  asm volatile("cp.async.wait_group 2;" ::: "memory")
#define CP_WAIT1()  asm volatile("cp.async.wait_group 1;" ::: "memory")
#define CP_WAIT0()  asm volatile("cp.async.wait_group 0;" ::: "memory")
#define CP_WAIT_REM(rem) do {                                           \
    if ((rem) >= 2) CP_WAIT2(); else if ((rem) == 1) CP_WAIT1();        \
    else CP_WAIT0();                                                    \
} while (0)

__device__ __forceinline__ void ldsm4(uint32_t* r, uint32_t a) {
    asm volatile("ldmatrix.sync.aligned.m8n8.x4.shared.b16 {%0,%1,%2,%3}, [%4];"
        : "=r"(r[0]), "=r"(r[1]), "=r"(r[2]), "=r"(r[3]) : "r"(a));
}
__device__ __forceinline__ void mma16816h(float* d, const uint32_t* a,
                                          uint32_t b0, uint32_t b1) {
    asm volatile("mma.sync.aligned.m16n8k16.row.col.f32.f16.f16.f32 "
        "{%0,%1,%2,%3}, {%4,%5,%6,%7}, {%8,%9}, {%0,%1,%2,%3};"
        : "+f"(d[0]), "+f"(d[1]), "+f"(d[2]), "+f"(d[3])
        : "r"(a[0]), "r"(a[1]), "r"(a[2]), "r"(a[3]), "r"(b0), "r"(b1));
}

// ===== fp16 1-pass scores GEMM: CTA 128x256, 16 warps, warp 64x32, 4-stage ==
constexpr int T_A = 0, T_B = 16384;
constexpr int BUFS = 49152;            // per stage: 16K A + 32K B
constexpr int GSMEMS = 4 * BUFS;       // 192 KB (epilogue needs 133632 < this)

__global__ void __launch_bounds__(512, 1)
mma_scores(const __half* __restrict__ Af, const __half* __restrict__ Bf,
           const float* __restrict__ bias)
{
    extern __shared__ __align__(128) char smem[];
    const int tid = threadIdx.x, wid = tid >> 5, lane = tid & 31;
    uint32_t sbase = smem_u32(smem);
    const int m0 = blockIdx.y * 128, n0 = blockIdx.x * 256;

    auto issue = [&](int c) {
        const int kc = c << 6;
        uint32_t sb = sbase + (c & 3) * BUFS;
#pragma unroll
        for (int i = 0; i < 2; i++) {
            const int idx = (i << 9) + tid;
            const int row = idx >> 3, seg = idx & 7;
            uint32_t so = sb + T_A + row * 128 + ((seg ^ (row & 7)) << 4);
            cp16(so, Af + (long long)(m0 + row) * 1024 + kc + seg * 8);
        }
#pragma unroll
        for (int i = 0; i < 4; i++) {
            const int idx = (i << 9) + tid;
            const int row = idx >> 3, seg = idx & 7;
            uint32_t so = sb + T_B + row * 128 + ((seg ^ (row & 7)) << 4);
            cp16(so, Bf + (long long)(n0 + row) * 1024 + kc + seg * 8);
        }
        CP_COMMIT();
    };

    issue(0); issue(1); issue(2);

    const int wm = (wid & 1) * 64, wn = (wid >> 1) * 32;
    const int arow  = wm + (lane & 15);
    const int akseg = lane >> 4;
    const int r7a   = arow & 7;
    const int brin  = ((lane >> 4) << 3) + (lane & 7);
    const int bkseg = (lane >> 3) & 1;
    const int r7b   = lane & 7;

    float acc[4][4][4];
#pragma unroll
    for (int a = 0; a < 4; a++)
#pragma unroll
        for (int b = 0; b < 4; b++)
#pragma unroll
            for (int q = 0; q < 4; q++) acc[a][b][q] = 0.f;

    for (int c = 0; c < 16; c++) {
        CP_WAIT_REM(15 - c);
        __syncthreads();
        uint32_t sb = sbase + (c & 3) * BUFS;
#pragma unroll
        for (int ks = 0; ks < 4; ks++) {
            const int ks2 = ks * 2;
            uint32_t ah[4][4], bh[2][4];
#pragma unroll
            for (int mt = 0; mt < 4; mt++) {
                uint32_t ao = sb + T_A + (arow + mt * 16) * 128
                            + (uint32_t)((((ks2 + akseg) ^ r7a)) << 4);
                ldsm4(ah[mt], ao);
            }
#pragma unroll
            for (int p = 0; p < 2; p++) {
                const int row = wn + p * 16 + brin;
                uint32_t bo = sb + T_B + row * 128
                            + (uint32_t)((((ks2 + bkseg) ^ r7b)) << 4);
                ldsm4(bh[p], bo);
            }
#pragma unroll
            for (int mt = 0; mt < 4; mt++)
#pragma unroll
                for (int nt = 0; nt < 4; nt++) {
                    const int p = nt >> 1, hb = (nt & 1) * 2;
                    mma16816h(acc[mt][nt], ah[mt], bh[p][hb], bh[p][hb + 1]);
                }
        }
        if (c + 3 < 16) issue(c + 3);
    }
    __syncthreads();   // all reads done before smem reuse by epilogue

    const int rr = lane >> 2, cc = (lane & 3) * 2;
    // ---- fused softmax over m + norm + fp16 dual-layout stores ----
    float* sf = (float*)smem;                 // 128 x 256, pitch 261
#pragma unroll
    for (int mt = 0; mt < 4; mt++) {
#pragma unroll
        for (int nt = 0; nt < 4; nt++) {
            int r = wm + mt * 16 + rr;
            int col = wn + nt * 8 + cc;
            float2 b2 = *(const float2*)(bias + n0 + col);
            sf[r * 261 + col]           = acc[mt][nt][0] + b2.x;
            sf[r * 261 + col + 1]       = acc[mt][nt][1] + b2.y;
            sf[(r + 8) * 261 + col]     = acc[mt][nt][2] + b2.x;
            sf[(r + 8) * 261 + col + 1] = acc[mt][nt][3] + b2.y;
        }
    }
    __syncthreads();
    {
        int row = tid & 127, hq = tid >> 7;
        size_t bn = (size_t)m0 + row;
        int headg = (n0 >> 6) + hq;
        float inv_t = 1.0f / g_T[bn * 16 + headg];
        float* rp = sf + row * 261 + hq * 64;
        float mx = -1e30f;
#pragma unroll 8
        for (int i = 0; i < 64; i++) mx = fmaxf(mx, rp[i]);
        float sum = 0.f;
#pragma unroll 8
        for (int i = 0; i < 64; i++) {
            float e = expf((rp[i] - mx) * inv_t);
            rp[i] = e; sum += e;
        }
        float inv = 1.0f / sum;
#pragma unroll 8
        for (int i = 0; i < 64; i++) rp[i] *= inv;
    }
    __syncthreads();
    const int bidx = m0 >> 13;
    if (tid < 256) {
        float s = 0.f;
#pragma unroll 8
        for (int i = 0; i < 128; i++) s += sf[i * 261 + tid];
        atomicAdd(&g_norm[bidx * 1024 + n0 + tid], s);
    }
#pragma unroll
    for (int i = 0; i < 32; i++) {
        int p = i * 512 + tid;
        int row = p >> 7, col = (p & 127) << 1;
        float w0 = sf[row * 261 + col], w1 = sf[row * 261 + col + 1];
        size_t o = ((size_t)m0 + row) * 1024 + n0 + col;
        *(__half2*)(g_Sf + o) = __floats2half2_rn(w0, w1);
    }
    {
        int nb = m0 & 8191;
#pragma unroll
        for (int i = 0; i < 32; i++) {
            int p = i * 512 + tid;
            int hm = p >> 6, n2 = (p & 63) << 1;
            float w0 = sf[n2 * 261 + hm], w1 = sf[(n2 + 1) * 261 + hm];
            size_t o = ((size_t)bidx * 1024 + n0 + hm) * 8192 + nb + n2;
            *(__half2*)(g_Sft + o) = __floats2half2_rn(w0, w1);
        }
    }
}

// ===== fp16 1-pass GEMM (y/out): CTA 128x256, 16 warps, 4-stage ring ========
constexpr int S1_A = 0, S1_B = 16384;
constexpr int BUF1 = 49152;
constexpr int GSMEM1 = 4 * BUF1;   // 192 KB

template<int EPI>   // 0 = plain store (K-split partials), 1 = bias + store
__global__ void __launch_bounds__(512, 1)
mma1_gemm(const __half* __restrict__ A, const __half* __restrict__ B,
          float* __restrict__ C, const float* __restrict__ bias,
          int Kdim, int lda, int ldb, int ldc,
          long long sA, long long sB, long long sC, long long sCk, int ksl)
{
    extern __shared__ __align__(128) char smem[];
    const int tid = threadIdx.x, wid = tid >> 5, lane = tid & 31;
    uint32_t sbase = smem_u32(smem);
    const long long zz = blockIdx.z;
    const long long batch = zz >> ksl;
    const long long kidx = zz & ((1 << ksl) - 1);
    A += batch * sA + kidx * (long long)Kdim;
    B += batch * sB + kidx * (long long)Kdim;
    C += batch * sC + kidx * sCk;
    const int m0 = blockIdx.y * 128, n0 = blockIdx.x * 256;

    auto issue = [&](int c) {
        const int kc = c << 6;
        uint32_t sb = sbase + (c & 3) * BUF1;
#pragma unroll
        for (int i = 0; i < 2; i++) {
            const int idx = (i << 9) + tid;
            const int row = idx >> 3, seg = idx & 7;
            uint32_t so = sb + S1_A + row * 128 + ((seg ^ (row & 7)) << 4);
            cp16(so, A + (long long)(m0 + row) * lda + kc + seg * 8);
        }
#pragma unroll
        for (int i = 0; i < 4; i++) {
            const int idx = (i << 9) + tid;
            const int row = idx >> 3, seg = idx & 7;
            uint32_t so = sb + S1_B + row * 128 + ((seg ^ (row & 7)) << 4);
            cp16(so, B + (long long)(n0 + row) * ldb + kc + seg * 8);
        }
        CP_COMMIT();
    };

    const int NC = Kdim >> 6;
    issue(0); issue(1); issue(2);

    const int wm = (wid & 1) * 64, wn = (wid >> 1) * 32;
    const int arow  = wm + (lane & 15);
    const int akseg = lane >> 4;
    const int r7a   = arow & 7;
    const int brin  = ((lane >> 4) << 3) + (lane & 7);
    const int bkseg = (lane >> 3) & 1;
    const int r7b   = lane & 7;

    float acc[4][4][4];
#pragma unroll
    for (int a = 0; a < 4; a++)
#pragma unroll
        for (int b = 0; b < 4; b++)
#pragma unroll
            for (int q = 0; q < 4; q++) acc[a][b][q] = 0.f;

    for (int c = 0; c < NC; c++) {
        CP_WAIT_REM(NC - 1 - c);
        __syncthreads();
        uint32_t sb = sbase + (c & 3) * BUF1;
#pragma unroll
        for (int ks = 0; ks < 4; ks++) {
            const int ks2 = ks * 2;
            uint32_t ah[4][4], bh[2][4];
#pragma unroll
            for (int mt = 0; mt < 4; mt++) {
                uint32_t ao = sb + S1_A + (arow + mt * 16) * 128
                            + (uint32_t)((((ks2 + akseg) ^ r7a)) << 4);
                ldsm4(ah[mt], ao);
            }
#pragma unroll
            for (int p = 0; p < 2; p++) {
                const int row = wn + p * 16 + brin;
                uint32_t bo = sb + S1_B + row * 128
                            + (uint32_t)((((ks2 + bkseg) ^ r7b)) << 4);
                ldsm4(bh[p], bo);
            }
#pragma unroll
            for (int mt = 0; mt < 4; mt++)
#pragma unroll
                for (int nt = 0; nt < 4; nt++) {
                    const int p = nt >> 1, hb = (nt & 1) * 2;
                    mma16816h(acc[mt][nt], ah[mt], bh[p][hb], bh[p][hb + 1]);
                }
        }
        if (c + 3 < NC) issue(c + 3);
    }

    const int rr = lane >> 2, cc = (lane & 3) * 2;
#pragma unroll
    for (int mt = 0; mt < 4; mt++) {
        const long long m = m0 + wm + mt * 16 + rr;
#pragma unroll
        for (int nt = 0; nt < 4; nt++) {
            const int n = n0 + wn + nt * 8 + cc;
            float bx = 0.f, by = 0.f;
            if (EPI == 1) {
                float2 b2 = *(const float2*)(bias + n);
                bx = b2.x; by = b2.y;
            }
            float2 v0 = make_float2(acc[mt][nt][0] + bx, acc[mt][nt][1] + by);
            float2 v1 = make_float2(acc[mt][nt][2] + bx, acc[mt][nt][3] + by);
            *(float2*)(C + m * ldc + n)       = v0;
            *(float2*)(C + (m + 8) * ldc + n) = v1;
        }
    }
}

// ============ temperature GEMM: fp16 single-pass (2-stage, small) ============
constexpr int TG_BUF = 16384;
constexpr int TG_B = 32768;
constexpr int TGSMEM = 65536;

__global__ void __launch_bounds__(256, 1)
k_tempmma(const __half* __restrict__ xf, const float* __restrict__ b_temp)
{
    extern __shared__ __align__(128) char smem[];
    const int tid = threadIdx.x, wid = tid >> 5, lane = tid & 31;
    uint32_t sbase = smem_u32(smem);
    const int m0 = blockIdx.x * 128;

#pragma unroll
    for (int q = 0; q < 8; q++) {
        int i = q * 256 + tid;
        int c = i >> 7, r = (i >> 3) & 15, seg = i & 7;
        uint32_t so = sbase + TG_B + c * 2048 + r * 128 + ((seg ^ (r & 7)) << 4);
        cp16(so, g_wtf + r * 1024 + c * 64 + seg * 8);
    }

    auto issueA = [&](int c) {
        uint32_t sb = sbase + (c & 1) * TG_BUF;
        const int kc = c << 6;
#pragma unroll
        for (int q = 0; q < 4; q++) {
            int i = q * 256 + tid;
            int row = i >> 3, seg = i & 7;
            uint32_t so = sb + row * 128 + ((seg ^ (row & 7)) << 4);
            cp16(so, xf + (long long)(m0 + row) * 1024 + kc + seg * 8);
        }
        CP_COMMIT();
    };
    issueA(0);

    const int wm = wid * 16;
    const int arow  = wm + (lane & 15);
    const int akseg = lane >> 4;
    const int r7a   = arow & 7;
    const int brow  = ((lane >> 4) << 3) + (lane & 7);
    const int bkseg = (lane >> 3) & 1;
    const int r7b   = brow & 7;

    float acc[2][4];
#pragma unroll
    for (int nt = 0; nt < 2; nt++)
#pragma unroll
        for (int q = 0; q < 4; q++) acc[nt][q] = 0.f;

    for (int c = 0; c < 16; c++) {
        if (c + 1 < 16) { issueA(c + 1); CP_WAIT1(); } else { CP_WAIT0(); }
        __syncthreads();
        uint32_t sa = sbase + (c & 1) * TG_BUF;
        uint32_t sbb = sbase + TG_B + c * 2048;
#pragma unroll
        for (int ks = 0; ks < 4; ks++) {
            const int ks2 = ks * 2;
            uint32_t ah[4], bh[4];
            uint32_t ao = sa + arow * 128 + (uint32_t)((((ks2 + akseg) ^ r7a)) << 4);
            ldsm4(ah, ao);
            uint32_t bo = sbb + brow * 128 + (uint32_t)((((ks2 + bkseg) ^ r7b)) << 4);
            ldsm4(bh, bo);
#pragma unroll
            for (int nt = 0; nt < 2; nt++) {
                const int hb = nt * 2;
                mma16816h(acc[nt], ah, bh[hb], bh[hb + 1]);
            }
        }
        __syncthreads();
    }

    const int rr = lane >> 2, cc = (lane & 3) * 2;
    const long long r0 = m0 + wm + rr, r1 = r0 + 8;
#pragma unroll
    for (int nt = 0; nt < 2; nt++) {
        int head = nt * 8 + cc;
        float b0 = b_temp[head], b1 = b_temp[head + 1];
        float v[4] = {acc[nt][0] + b0, acc[nt][1] + b1,
                      acc[nt][2] + b0, acc[nt][3] + b1};
#pragma unroll
        for (int q = 0; q < 4; q++) {
            float s = v[q];
            v[q] = 0.5f + fmaxf(s, 0.f) + log1pf(expf(-fabsf(s)));
        }
        g_T[r0 * 16 + head]     = v[0];
        g_T[r0 * 16 + head + 1] = v[1];
        g_T[r1 * 16 + head]     = v[2];
        g_T[r1 * 16 + head + 1] = v[3];
    }
}

// ============ fused prologue: convx | prep | wsplit | zero ============
__global__ void __launch_bounds__(256)
k_aux(const float* __restrict__ x, const float* __restrict__ xq,
      const float* __restrict__ w_kv, const float* __restrict__ b_kv,
      const float* __restrict__ w_temp)
{
    __shared__ float xs[64][67];
    const int bid = blockIdx.x;
    const int t = threadIdx.x;

    if (bid < 8192) {
        const int jt = bid & 15, nt = bid >> 4;
#pragma unroll
        for (int q = 0; q < 4; q++) {
            int lin = q * 256 + t;
            int row = lin >> 4, c4 = (lin & 15) << 2;
            float4 v = *(const float4*)(x + ((size_t)nt * 64 + row) * 1024 + jt * 64 + c4);
            xs[row][c4 + 0] = v.x; xs[row][c4 + 1] = v.y;
            xs[row][c4 + 2] = v.z; xs[row][c4 + 3] = v.w;
        }
        __syncthreads();
#pragma unroll
        for (int q = 0; q < 8; q++) {
            int lin = q * 256 + t;
            int row = lin >> 5, col = (lin & 31) << 1;
            size_t o = ((size_t)nt * 64 + row) * 1024 + jt * 64 + col;
            *(__half2*)(g_xfh + o) = __floats2half2_rn(xs[row][col], xs[row][col + 1]);
        }
        const int b = (nt * 64) >> 13, nn0 = (nt * 64) & 8191;
#pragma unroll
        for (int q = 0; q < 8; q++) {
            int lin = q * 256 + t;
            int j = lin >> 5, n2 = (lin & 31) << 1;
            size_t o = ((size_t)(b * 1024 + jt * 64 + j)) * 8192 + nn0 + n2;
            *(__half2*)(g_xtf + o) = __floats2half2_rn(xs[n2][j], xs[n2 + 1][j]);
        }
    } else if (bid < 12288) {
        int idx = (bid - 8192) * 256 + t;
        int j = idx >> 10, hm = idx & 1023;
        int hbase = (hm >> 6) << 6;
        const float* xr = xq + (size_t)hm * 64;
        const float* wr = w_kv + (size_t)j * 2048 + hbase;
        float acc = 0.f;
#pragma unroll 8
        for (int d = 0; d < 64; d++) acc += xr[d] * wr[d];
        g_Atf[(size_t)hm * 1024 + j] = __float2half(acc);
        if (j == 0) {
            const float* br = b_kv + hbase;
            float cc = 0.f;
            for (int d = 0; d < 64; d++) cc += xr[d] * br[d];
            g_c[hm] = cc;
        }
    } else if (bid < 12352) {
        int idx = (bid - 12288) * 256 + t;
        int h = idx >> 10, j = idx & 1023;
        g_wtf[idx] = __float2half(w_temp[j * 16 + h]);
    } else {
        int i = (bid - 12352) * 256 + t;
        if (i < cB * cHM) g_norm[i] = 0.f;
    }
}

// ============ reduce 8 y-partials into partial 0 ============
__global__ void __launch_bounds__(256)
k_yred()
{
    constexpr size_t YPS4 = (size_t)cB * cHM * cH / 4;
    size_t i = (size_t)blockIdx.x * 256 + threadIdx.x;
    float4* base = (float4*)g_yp;
    float4 s = base[i];
#pragma unroll
    for (int p = 1; p < 8; p++) {
        float4 v = base[p * YPS4 + i];
        s.x += v.x; s.y += v.y; s.z += v.z; s.w += v.w;
    }
    base[i] = s;
}

// ======= fused slice_token + tiny qkv attention: one block per (b,h) ========
__global__ void __launch_bounds__(256)
k_stq(const float* __restrict__ w_kv, const float* __restrict__ b_kv,
      const float* __restrict__ qkv_proj)
{
    int z = blockIdx.x;
    int b = z >> 4, h = z & 15;
    const float* Yb = g_yp + ((size_t)b * 1024 + h * 64) * 1024;
    const float* Wv = w_kv + 1024 + h * 64;
    __shared__ float As[16][64];
    __shared__ float Bs[16][64];
    __shared__ float sst[64][65];
    int t = threadIdx.x;
    int tyy = t >> 4, txx = t & 15;
    float acc[4][4] = {};
    for (int k0 = 0; k0 < 1024; k0 += 16) {
        {
            int m = t >> 2, k4 = (t & 3) << 2;
            float4 v = *(const float4*)(Yb + (size_t)m * 1024 + k0 + k4);
            As[k4 + 0][m] = v.x; As[k4 + 1][m] = v.y;
            As[k4 + 2][m] = v.z; As[k4 + 3][m] = v.w;
        }
        {
            int k = t >> 4, n4 = (t & 15) << 2;
            *(float4*)&Bs[k][n4] = *(const float4*)(Wv + (size_t)(k0 + k) * 2048 + n4);
        }
        __syncthreads();
#pragma unroll
        for (int kk = 0; kk < 16; kk++) {
            float4 a  = *(const float4*)&As[kk][tyy * 4];
            float4 bb = *(const float4*)&Bs[kk][txx * 4];
            float av[4] = {a.x, a.y, a.z, a.w};
            float bv[4] = {bb.x, bb.y, bb.z, bb.w};
#pragma unroll
            for (int i = 0; i < 4; i++)
#pragma unroll
                for (int jj = 0; jj < 4; jj++) acc[i][jj] += av[i] * bv[jj];
        }
        __syncthreads();
    }
#pragma unroll
    for (int i = 0; i < 4; i++) {
        int m = tyy * 4 + i;
        float nrm = g_norm[b * 1024 + h * 64 + m];
        float inv = 1.0f / (nrm + 1e-5f);
#pragma unroll
        for (int jj = 0; jj < 4; jj++) {
            int d = txx * 4 + jj;
            float bvv = b_kv[1024 + h * 64 + d];
            sst[m][d] = (acc[i][jj] + nrm * bvv) * inv;
        }
    }
    __syncthreads();

    // tiny qkv attention: 16 iterations x 4 m-rows; thread = (ml, d)
    const float* P = qkv_proj + (size_t)h * 64 * 192;
    __shared__ float ex[4][64];
    __shared__ float red[4][2];
    const int ml = t >> 6, d = t & 63;
    for (int it = 0; it < 16; it++) {
        const int m = it * 4 + ml;
        float q = 0.f, k = 0.f, v = 0.f;
#pragma unroll 8
        for (int j = 0; j < 64; j++) {
            float s = sst[m][j];
            const float* pr = P + j * 192;
            q += s * pr[d]; k += s * pr[64 + d]; v += s * pr[128 + d];
        }
        float dot = q * k * 0.125f;
        ex[ml][d] = dot;
        __syncthreads();
        float mx = -1e30f;
#pragma unroll 8
        for (int j = 0; j < 64; j++) mx = fmaxf(mx, ex[ml][j]);
        __syncthreads();
        float e = expf(dot - mx);
        ex[ml][d] = e;
        __syncthreads();
        float sum = 0.f;
#pragma unroll 8
        for (int j = 0; j < 64; j++) sum += ex[ml][j];
        g_ost[((size_t)z * 64 + m) * 64 + d] = (e / sum) * v;
        __syncthreads();
    }
    (void)red;
}

__global__ void __launch_bounds__(256)
k_zmat(const float* __restrict__ w_out)
{
    int z = blockIdx.y, jc = blockIdx.x;
    int b = z >> 4, h = z & 15;
    __shared__ float As[64][64];
    __shared__ float Bs[64][64];
    int t = threadIdx.x;
#pragma unroll
    for (int r = 0; r < 4; r++) {
        int lin = t + r * 256;
        int row = lin >> 4;
        int c4  = (lin & 15) << 2;
        float4 v = *(const float4*)(g_ost + ((size_t)z * 64 + row) * 64 + c4);
        As[c4 + 0][row] = v.x; As[c4 + 1][row] = v.y;
        As[c4 + 2][row] = v.z; As[c4 + 3][row] = v.w;
        *(float4*)&Bs[row][c4] =
            *(const float4*)(w_out + (size_t)(h * 64 + row) * 1024 + jc * 64 + c4);
    }
    __syncthreads();
    int tyy = t >> 4, txx = t & 15;
    float acc[4][4] = {};
#pragma unroll
    for (int kk = 0; kk < 64; kk++) {
        float4 a  = *(const float4*)&As[kk][tyy * 4];
        float4 bb = *(const float4*)&Bs[kk][txx * 4];
        float av[4] = {a.x, a.y, a.z, a.w};
        float bv[4] = {bb.x, bb.y, bb.z, bb.w};
#pragma unroll
        for (int i = 0; i < 4; i++)
#pragma unroll
            for (int jj = 0; jj < 4; jj++) acc[i][jj] += av[i] * bv[jj];
    }
#pragma unroll
    for (int i = 0; i < 4; i++) {
        int hm = h * 64 + tyy * 4 + i;
#pragma unroll
        for (int jj = 0; jj < 4; jj++) {
            int j = jc * 64 + txx * 4 + jj;
            g_Ztf[((size_t)b * 1024 + j) * 1024 + hm] = __float2half(acc[i][jj]);
        }
    }
}

// ---------------------------------------------------------------------------
extern "C" void kernel_launch(void* const* d_in, const int* in_sizes, int n_in,
                              void* d_out, int out_size)
{
    (void)in_sizes; (void)n_in; (void)out_size;
    const float* x      = (const float*)d_in[0];
    const float* w_kv   = (const float*)d_in[2];
    const float* b_kv   = (const float*)d_in[3];
    const float* w_temp = (const float*)d_in[4];
    const float* b_temp = (const float*)d_in[5];
    const float* xq     = (const float*)d_in[6];
    const float* qkv_p  = (const float*)d_in[7];
    const float* w_out  = (const float*)d_in[8];
    const float* b_out  = (const float*)d_in[9];
    float* out = (float*)d_out;

    float *pc, *pyp;
    __half *pxfh, *pxtf, *pSf, *pSft, *pAtf, *pZtf;
    cudaGetSymbolAddress((void**)&pc,  g_c);
    cudaGetSymbolAddress((void**)&pyp, g_yp);
    cudaGetSymbolAddress((void**)&pxfh, g_xfh);
    cudaGetSymbolAddress((void**)&pxtf, g_xtf);
    cudaGetSymbolAddress((void**)&pSf, g_Sf);   cudaGetSymbolAddress((void**)&pSft, g_Sft);
    cudaGetSymbolAddress((void**)&pAtf, g_Atf);
    cudaGetSymbolAddress((void**)&pZtf, g_Ztf);

    cudaFuncSetAttribute(mma_scores,   cudaFuncAttributeMaxDynamicSharedMemorySize, GSMEMS);
    cudaFuncSetAttribute(mma1_gemm<0>, cudaFuncAttributeMaxDynamicSharedMemorySize, GSMEM1);
    cudaFuncSetAttribute(mma1_gemm<1>, cudaFuncAttributeMaxDynamicSharedMemorySize, GSMEM1);
    cudaFuncSetAttribute(k_tempmma,    cudaFuncAttributeMaxDynamicSharedMemorySize, TGSMEM);

    // fused prologue: convx + prep + wsplit + zero
    k_aux<<<12368, 256>>>(x, xq, w_kv, b_kv, w_temp);
    k_tempmma<<<256, 256, TGSMEM>>>(pxfh, b_temp);
    // scores (fp16 single-pass, 4-stage) + fused softmax/norm/fp16 stores
    mma_scores<<<dim3(4, 256, 1), 512, GSMEMS>>>(pxfh, pAtf, pc);
    // y[b] = S[b]^T @ x[b] (fp16 single-pass, 4-stage), K-split x8
    mma1_gemm<0><<<dim3(4, 8, cB * 8), 512, GSMEM1>>>(
        pSft, pxtf, pyp, nullptr,
        1024, 8192, 8192, 1024,
        (long long)cHM * cN, (long long)cH * cN,
        (long long)cHM * cH, (long long)cB * cHM * cH, 3);
    k_yred<<<4096, 256>>>();
    // fused slice_token + tiny qkv
    k_stq<<<cB * cNH, 256>>>(w_kv, b_kv, qkv_p);
    k_zmat<<<dim3(16, cB * cNH), 256>>>(w_out);
    // out[b] = S[b] @ Zt[b]^T + b_out (fp16 single-pass, 4-stage)
    mma1_gemm<1><<<dim3(4, 64, cB), 512, GSMEM1>>>(
        pSf, pZtf, out, b_out,
        1024, 1024, 1024, 1024,
        (long long)cN * cHM, (long long)cH * cHM,
        (long long)cN * cH, 0, 0);
}